// round 15
// baseline (speedup 1.0000x reference)
#include <cuda_runtime.h>
#include <cstdint>

// Problem constants
//  H=8, KB=8 cells; OB=64, IB=64, K=9, L=9; ZD=64, PD=16, DH=128
//  out: [512, 512, 9, 9] fp32 = 21,233,664 elements

__device__ float g_hid[64 * 128];   // relu(x @ W1^T + b1)
__device__ int   g_ready;           // hid producer arrivals (0..4), reset on exit
__device__ int   g_done;            // block exit count, reset on exit

// Packed f32x2 FMA (sm_103a)
#define FMA_F32X2(d, a, b, c) \
    asm("fma.rn.f32x2 %0, %1, %2, %3;" : "=l"(d) : "l"(a), "l"(b), "l"(c))

__device__ __forceinline__ uint32_t smem_u32(const void* p) {
    uint32_t a;
    asm("{ .reg .u64 t; cvta.to.shared.u64 t, %1; cvt.u32.u64 %0, t; }" : "=r"(a) : "l"(p));
    return a;
}
#define CP_ASYNC16(dst, src) \
    asm volatile("cp.async.cg.shared.global [%0], [%1], 16;" :: "r"(dst), "l"(src))
#define CP_COMMIT() asm volatile("cp.async.commit_group;" ::: "memory")
#define CP_WAIT1()  asm volatile("cp.async.wait_group 1;" ::: "memory")
#define CP_WAIT0()  asm volatile("cp.async.wait_group 0;" ::: "memory")

// ---------------------------------------------------------------------------
// Single fused kernel = R12 fused_weight_gen + in-kernel hid production.
// grid 512: blockIdx.x = ob*8 + ibg ; block 128: cg = tid>>3 (4 cells), ibl = tid&7
//
// smem pool (floats), dynamic, 54,528 B (13632 floats):
//   producer phase (blocks 0..3): xs_all[16][80] @0  (disjoint from wb0/wb1)
//   GEMM: hs[64][132] @0, wb0[72][36] @8448, wb1[72][36] @11040
//   epilogue aliases: exe_s[64][72] @0, un_s[64][72] @4608
// cp.async groups: G0 = W2 chunk0, G1 = W2 chunk1, G2 = hid  -> WAIT0 before GEMM.
// In-loop refills then use the same COMMIT/WAIT1 pattern as R12.
// ---------------------------------------------------------------------------
__global__ __launch_bounds__(128)
void fused_all(const float* __restrict__ z_all,
               const float* __restrict__ W1,
               const float* __restrict__ b1,
               const float* __restrict__ pde,
               const float* __restrict__ W2,
               const float* __restrict__ b2,
               const float* __restrict__ unet,
               float* __restrict__ out)
{
    extern __shared__ float sm[];
    float* hs    = sm;               // [64][132]
    float* wb0   = sm + 8448;        // [72][36]
    float* wb1   = sm + 11040;       // [72][36]
    float* exe_s = sm;               // [64][72] alias
    float* un_s  = sm + 4608;        // [64][72] alias

    const int tid    = threadIdx.x;
    const int ob     = blockIdx.x >> 3;
    const int ibg    = blockIdx.x & 7;
    const int ibbase = ibg * 8;
    const int base9  = (ob * 64 + ibbase) * 9;   // 72 contiguous W2 rows

    const int cg  = tid >> 3;   // cells cg*4 .. cg*4+3
    const int ibl = tid & 7;

    const uint32_t hs_u  = smem_u32(hs);
    const uint32_t wb0_u = smem_u32(wb0);
    const uint32_t wb1_u = smem_u32(wb1);

    // ---- 1) W2 prefetch first (no hid dependency): chunk0 -> G0, chunk1 -> G1
    for (int idx = tid; idx < 576; idx += 128) {
        int row = idx >> 3, q = idx & 7;
        CP_ASYNC16(wb0_u + (uint32_t)(row * 36 + 4 * q) * 4u,
                   (const void*)(W2 + (size_t)(base9 + row) * 128 + 4 * q));
    }
    CP_COMMIT();
    for (int idx = tid; idx < 576; idx += 128) {
        int row = idx >> 3, q = idx & 7;
        CP_ASYNC16(wb1_u + (uint32_t)(row * 36 + 4 * q) * 4u,
                   (const void*)(W2 + (size_t)(base9 + row) * 128 + 32 + 4 * q));
    }
    CP_COMMIT();

    // ---- 2) hid producers: blocks 0..3, 16 rows each (xs region < wb0) ----
    if (blockIdx.x < 4) {
        const int rb = blockIdx.x * 16;
        for (int idx = tid; idx < 1024; idx += 128) {
            int row = idx >> 6, c = idx & 63;
            sm[row * 80 + c] = z_all[(rb + row) * 64 + c];
        }
        for (int idx = tid; idx < 256; idx += 128) {
            int row = idx >> 4, c = idx & 15;
            sm[row * 80 + 64 + c] = pde[c];
        }
        __syncthreads();
        const float4* wrow = (const float4*)(W1 + tid * 80);
        const float b1j = b1[tid];
#pragma unroll 1
        for (int r = 0; r < 16; ++r) {
            const float* xr = sm + r * 80;
            float a0 = b1j, a1 = 0.f, a2 = 0.f, a3 = 0.f;   // 4 chains
#pragma unroll
            for (int t = 0; t < 20; t += 4) {
                float4 w0 = wrow[t],   w1 = wrow[t+1];
                float4 w2 = wrow[t+2], w3 = wrow[t+3];
                a0 = fmaf(w0.x, xr[4*t+0], a0);  a0 = fmaf(w0.y, xr[4*t+1], a0);
                a0 = fmaf(w0.z, xr[4*t+2], a0);  a0 = fmaf(w0.w, xr[4*t+3], a0);
                a1 = fmaf(w1.x, xr[4*t+4], a1);  a1 = fmaf(w1.y, xr[4*t+5], a1);
                a1 = fmaf(w1.z, xr[4*t+6], a1);  a1 = fmaf(w1.w, xr[4*t+7], a1);
                a2 = fmaf(w2.x, xr[4*t+8], a2);  a2 = fmaf(w2.y, xr[4*t+9], a2);
                a2 = fmaf(w2.z, xr[4*t+10], a2); a2 = fmaf(w2.w, xr[4*t+11], a2);
                a3 = fmaf(w3.x, xr[4*t+12], a3); a3 = fmaf(w3.y, xr[4*t+13], a3);
                a3 = fmaf(w3.z, xr[4*t+14], a3); a3 = fmaf(w3.w, xr[4*t+15], a3);
            }
            g_hid[(rb + r) * 128 + tid] = fmaxf((a0 + a1) + (a2 + a3), 0.0f);
        }
        __threadfence();
        __syncthreads();
        if (tid == 0) atomicAdd(&g_ready, 1);
    }

    // ---- 3) wait for hid (overlaps our W2 loads in flight) ----
    if (tid == 0) {
        while (atomicAdd(&g_ready, 0) < 4) __nanosleep(64);
    }
    __syncthreads();

    // ---- 4) hid cp.async -> G2 ----
    for (int idx = tid; idx < 2048; idx += 128) {
        int c = idx >> 5, q = idx & 31;
        CP_ASYNC16(hs_u + (uint32_t)(c * 132 + 4 * q) * 4u,
                   (const void*)(g_hid + c * 128 + 4 * q));
    }
    CP_COMMIT();

    unsigned long long acc[4][9];
#pragma unroll
    for (int j = 0; j < 4; ++j)
#pragma unroll
        for (int k = 0; k < 9; ++k) acc[j][k] = 0ull;

    CP_WAIT0();          // hs + both W2 chunks resident
    __syncthreads();

    const float* hp0 = hs + (cg * 4) * 132;
    const float* hp1 = hp0 + 132;
    const float* hp2 = hp0 + 264;
    const float* hp3 = hp0 + 396;

    // ---- GEMM: 4 chunks of 32 d, double buffered (identical to R12) ----
#pragma unroll 1
    for (int c = 0; c < 4; ++c) {
        const float* wp = ((c & 1) ? wb1 : wb0) + ibl * 324;
        const int cb = c * 32;
#pragma unroll
        for (int dd = 0; dd < 32; dd += 4) {
            ulonglong2 h0 = *(const ulonglong2*)(hp0 + cb + dd);
            ulonglong2 h1 = *(const ulonglong2*)(hp1 + cb + dd);
            ulonglong2 h2 = *(const ulonglong2*)(hp2 + cb + dd);
            ulonglong2 h3 = *(const ulonglong2*)(hp3 + cb + dd);
#pragma unroll
            for (int k = 0; k < 9; ++k) {
                ulonglong2 w = *(const ulonglong2*)(wp + k * 36 + dd);
                FMA_F32X2(acc[0][k], h0.x, w.x, acc[0][k]);
                FMA_F32X2(acc[0][k], h0.y, w.y, acc[0][k]);
                FMA_F32X2(acc[1][k], h1.x, w.x, acc[1][k]);
                FMA_F32X2(acc[1][k], h1.y, w.y, acc[1][k]);
                FMA_F32X2(acc[2][k], h2.x, w.x, acc[2][k]);
                FMA_F32X2(acc[2][k], h2.y, w.y, acc[2][k]);
                FMA_F32X2(acc[3][k], h3.x, w.x, acc[3][k]);
                FMA_F32X2(acc[3][k], h3.y, w.y, acc[3][k]);
            }
        }
        __syncthreads();
        if (c < 2) {
            uint32_t bu = (c & 1) ? wb1_u : wb0_u;
            const float* src = W2 + (c + 2) * 32;
            for (int idx = tid; idx < 576; idx += 128) {
                int row = idx >> 3, q = idx & 7;
                CP_ASYNC16(bu + (uint32_t)(row * 36 + 4 * q) * 4u,
                           (const void*)(src + (size_t)(base9 + row) * 128 + 4 * q));
            }
            CP_COMMIT();
            CP_WAIT1();
        } else if (c == 2) {
            CP_WAIT0();
        }
        if (c < 3) __syncthreads();
    }
    __syncthreads();   // protect exe_s/un_s aliases

    // ---- finalize exe into smem ----
#pragma unroll
    for (int k = 0; k < 9; ++k) {
        float bvk = b2[base9 + ibl * 9 + k];
#pragma unroll
        for (int j = 0; j < 4; ++j) {
            float2 p = *(float2*)&acc[j][k];
            exe_s[(cg * 4 + j) * 72 + ibl * 9 + k] = p.x + p.y + bvk;
        }
    }

    // ---- stage unet: per cell 72 contiguous floats = 18 float4 ----
    for (int idx = tid; idx < 1152; idx += 128) {
        int cell = idx / 18, q = idx - cell * 18;
        int h = cell >> 3, kb = cell & 7;
        size_t bu = ((size_t)(h * 64 + ob) * 512 + (size_t)(kb * 64 + ibbase)) * 9;
        *(float4*)(un_s + cell * 72 + 4 * q) = *(const float4*)(unet + bu + 4 * q);
    }
    __syncthreads();

    // ---- epilogue: cell-invariant indices (identical to R12) ----
    {
        const int e0 = tid * 4;
        int kkA[4], uuA[4], kkB[4], uuB[4];
#pragma unroll
        for (int t = 0; t < 4; ++t) {
            int e = e0 + t;
            kkA[t] = e / 9;
            uuA[t] = (e / 81) * 9 + (e % 9);
            int eb = e + 512;
            kkB[t] = eb / 9;
            uuB[t] = (eb / 81) * 9 + (eb % 9);
        }
        const bool second = (tid < 34);
        const float* esh = exe_s;
        const float* ush = un_s;
        float* outp = out + ((size_t)(ob * 512 + ibbase)) * 81 + e0;

#pragma unroll 1
        for (int h = 0; h < 8; ++h) {
#pragma unroll
            for (int kb = 0; kb < 8; ++kb) {
                const float* es = esh + kb * 72;
                const float* us = ush + kb * 72;
                float v0 = es[kkA[0]] * us[uuA[0]];
                float v1 = es[kkA[1]] * us[uuA[1]];
                float v2 = es[kkA[2]] * us[uuA[2]];
                float v3 = es[kkA[3]] * us[uuA[3]];
                *(float4*)(outp + kb * 5184) = make_float4(v0, v1, v2, v3);
                if (second) {
                    float w0 = es[kkB[0]] * us[uuB[0]];
                    float w1 = es[kkB[1]] * us[uuB[1]];
                    float w2 = es[kkB[2]] * us[uuB[2]];
                    float w3 = es[kkB[3]] * us[uuB[3]];
                    *(float4*)(outp + kb * 5184 + 512) = make_float4(w0, w1, w2, w3);
                }
            }
            esh  += 576;
            ush  += 576;
            outp += (size_t)64 * 512 * 81;
        }
    }

    // ---- exit: last block resets flags for next graph replay ----
    if (tid == 0) {
        __threadfence();
        int n = atomicAdd(&g_done, 1);
        if (n == 511) {
            g_ready = 0;
            g_done  = 0;
            __threadfence();
        }
    }
}

// ---------------------------------------------------------------------------
extern "C" void kernel_launch(void* const* d_in, const int* in_sizes, int n_in,
                              void* d_out, int out_size)
{
    const float* z_all = (const float*)d_in[0];   // [64, 64]
    const float* W1    = (const float*)d_in[1];   // [128, 80]
    const float* b1    = (const float*)d_in[2];   // [128]
    const float* W2    = (const float*)d_in[3];   // [36864, 128]
    const float* b2    = (const float*)d_in[4];   // [36864]
    const float* unet  = (const float*)d_in[5];   // [512, 512, 9]
    const float* pde   = (const float*)d_in[6];   // [16]
    float* out = (float*)d_out;                   // [512, 512, 9, 9]

    cudaFuncSetAttribute(fused_all,
                         cudaFuncAttributeMaxDynamicSharedMemorySize, 54528);

    fused_all<<<512, 128, 54528>>>(z_all, W1, b1, pde, W2, b2, unet, out);
}

// round 16
// speedup vs baseline: 1.1757x; 1.1757x over previous
#include <cuda_runtime.h>
#include <cstdint>

// Problem constants
//  H=8, KB=8 cells; OB=64, IB=64, K=9, L=9; ZD=64, PD=16, DH=128
//  out: [512, 512, 9, 9] fp32 = 21,233,664 elements

__device__ float g_hid[64 * 128];   // relu(x @ W1^T + b1)

// Packed f32x2 FMA (sm_103a)
#define FMA_F32X2(d, a, b, c) \
    asm("fma.rn.f32x2 %0, %1, %2, %3;" : "=l"(d) : "l"(a), "l"(b), "l"(c))

__device__ __forceinline__ uint32_t smem_u32(const void* p) {
    uint32_t a;
    asm("{ .reg .u64 t; cvta.to.shared.u64 t, %1; cvt.u32.u64 %0, t; }" : "=r"(a) : "l"(p));
    return a;
}
#define CP_ASYNC16(dst, src) \
    asm volatile("cp.async.cg.shared.global [%0], [%1], 16;" :: "r"(dst), "l"(src))
#define CP_COMMIT() asm volatile("cp.async.commit_group;" ::: "memory")
#define CP_WAIT1()  asm volatile("cp.async.wait_group 1;" ::: "memory")
#define CP_WAIT0()  asm volatile("cp.async.wait_group 0;" ::: "memory")

// ---------------------------------------------------------------------------
// Kernel 1: hid[r][j] = relu(b1[j] + sum_t x[r][t] * W1[j][t])
// ---------------------------------------------------------------------------
__global__ __launch_bounds__(128)
void hypernet_hid(const float* __restrict__ z_all,
                  const float* __restrict__ W1,
                  const float* __restrict__ b1,
                  const float* __restrict__ pde)
{
    __shared__ float xs[80];
    const int r = blockIdx.x;
    const int j = threadIdx.x;
    if (j < 64)       xs[j] = z_all[r * 64 + j];
    else if (j < 80)  xs[j] = pde[j - 64];
    __syncthreads();

    const float4* wp = (const float4*)(W1 + j * 80);
    float acc = b1[j];
#pragma unroll
    for (int t = 0; t < 20; ++t) {
        float4 w = wp[t];
        acc = fmaf(w.x, xs[4*t+0], acc);
        acc = fmaf(w.y, xs[4*t+1], acc);
        acc = fmaf(w.z, xs[4*t+2], acc);
        acc = fmaf(w.w, xs[4*t+3], acc);
    }
    g_hid[r * 128 + j] = fmaxf(acc, 0.0f);
}

// ---------------------------------------------------------------------------
// Kernel 2 (fused): 4-cell register tile; reg-capped to 128 -> 4 blocks/SM
// so all 512 blocks fit in ONE wave (prev: 138 regs -> 3/SM -> 68-block tail).
// grid 512: blockIdx.x = ob*8 + ibg
// block 128: tid = cg*8 + ibl   (cg in [0,16) -> 4 cells; ibl in [0,8))
//
// smem pool (floats), dynamic, 54,528 B (4 blocks * 54.5KB = 218KB <= 228KB):
//   hs  [64][132] @0      (8448)   hid, all K=128
//   wb0 [72][36]  @8448   (2592)   W2 chunks (32 d), double buffered
//   wb1 [72][36]  @11040  (2592)
//   epilogue aliases: exe_s[64][72] @0, un_s[64][72] @4608
// ---------------------------------------------------------------------------
__global__ __launch_bounds__(128, 4)
void fused_weight_gen(const float* __restrict__ W2,
                      const float* __restrict__ b2,
                      const float* __restrict__ unet,
                      float* __restrict__ out)
{
    extern __shared__ float sm[];
    float* hs    = sm;               // [64][132]
    float* wb0   = sm + 8448;        // [72][36]
    float* wb1   = sm + 11040;       // [72][36]
    float* exe_s = sm;               // [64][72] alias
    float* un_s  = sm + 4608;        // [64][72] alias

    const int tid    = threadIdx.x;
    const int ob     = blockIdx.x >> 3;
    const int ibg    = blockIdx.x & 7;
    const int ibbase = ibg * 8;
    const int base9  = (ob * 64 + ibbase) * 9;   // 72 contiguous W2 rows

    const int cg  = tid >> 3;   // cells cg*4 .. cg*4+3
    const int ibl = tid & 7;

    const uint32_t hs_u  = smem_u32(hs);
    const uint32_t wb0_u = smem_u32(wb0);
    const uint32_t wb1_u = smem_u32(wb1);

    // ---- prologue: async hid (ALL K=128: 32 float4/cell) + W2 chunk0 -> group0
    for (int idx = tid; idx < 2048; idx += 128) {
        int c = idx >> 5, q = idx & 31;
        CP_ASYNC16(hs_u + (uint32_t)(c * 132 + 4 * q) * 4u,
                   (const void*)(g_hid + c * 128 + 4 * q));
    }
    for (int idx = tid; idx < 576; idx += 128) {
        int row = idx >> 3, q = idx & 7;
        CP_ASYNC16(wb0_u + (uint32_t)(row * 36 + 4 * q) * 4u,
                   (const void*)(W2 + (size_t)(base9 + row) * 128 + 4 * q));
    }
    CP_COMMIT();
    // chunk1 -> group1
    for (int idx = tid; idx < 576; idx += 128) {
        int row = idx >> 3, q = idx & 7;
        CP_ASYNC16(wb1_u + (uint32_t)(row * 36 + 4 * q) * 4u,
                   (const void*)(W2 + (size_t)(base9 + row) * 128 + 32 + 4 * q));
    }
    CP_COMMIT();

    unsigned long long acc[4][9];
#pragma unroll
    for (int j = 0; j < 4; ++j)
#pragma unroll
        for (int k = 0; k < 9; ++k) acc[j][k] = 0ull;

    CP_WAIT1();          // group0 done: hs + chunk0 resident
    __syncthreads();

    const float* hp0 = hs + (cg * 4) * 132;
    const float* hp1 = hp0 + 132;
    const float* hp2 = hp0 + 264;
    const float* hp3 = hp0 + 396;

    // ---- GEMM: 4 chunks of 32 d, double buffered ----
#pragma unroll 1
    for (int c = 0; c < 4; ++c) {
        const float* wp = ((c & 1) ? wb1 : wb0) + ibl * 324;
        const int cb = c * 32;
#pragma unroll
        for (int dd = 0; dd < 32; dd += 4) {
            ulonglong2 h0 = *(const ulonglong2*)(hp0 + cb + dd);
            ulonglong2 h1 = *(const ulonglong2*)(hp1 + cb + dd);
            ulonglong2 h2 = *(const ulonglong2*)(hp2 + cb + dd);
            ulonglong2 h3 = *(const ulonglong2*)(hp3 + cb + dd);
#pragma unroll
            for (int k = 0; k < 9; ++k) {
                ulonglong2 w = *(const ulonglong2*)(wp + k * 36 + dd);
                FMA_F32X2(acc[0][k], h0.x, w.x, acc[0][k]);
                FMA_F32X2(acc[0][k], h0.y, w.y, acc[0][k]);
                FMA_F32X2(acc[1][k], h1.x, w.x, acc[1][k]);
                FMA_F32X2(acc[1][k], h1.y, w.y, acc[1][k]);
                FMA_F32X2(acc[2][k], h2.x, w.x, acc[2][k]);
                FMA_F32X2(acc[2][k], h2.y, w.y, acc[2][k]);
                FMA_F32X2(acc[3][k], h3.x, w.x, acc[3][k]);
                FMA_F32X2(acc[3][k], h3.y, w.y, acc[3][k]);
            }
        }
        __syncthreads();
        if (c < 2) {
            uint32_t bu = (c & 1) ? wb1_u : wb0_u;
            const float* src = W2 + (c + 2) * 32;
            for (int idx = tid; idx < 576; idx += 128) {
                int row = idx >> 3, q = idx & 7;
                CP_ASYNC16(bu + (uint32_t)(row * 36 + 4 * q) * 4u,
                           (const void*)(src + (size_t)(base9 + row) * 128 + 4 * q));
            }
            CP_COMMIT();
            CP_WAIT1();
        } else if (c == 2) {
            CP_WAIT0();
        }
        if (c < 3) __syncthreads();
    }
    __syncthreads();   // protect exe_s/un_s aliases over hs/wb

    // ---- finalize exe into smem ----
#pragma unroll
    for (int k = 0; k < 9; ++k) {
        float bvk = b2[base9 + ibl * 9 + k];
#pragma unroll
        for (int j = 0; j < 4; ++j) {
            float2 p = *(float2*)&acc[j][k];
            exe_s[(cg * 4 + j) * 72 + ibl * 9 + k] = p.x + p.y + bvk;
        }
    }

    // ---- stage unet: per cell 72 contiguous floats = 18 float4 ----
    for (int idx = tid; idx < 1152; idx += 128) {
        int cell = idx / 18, q = idx - cell * 18;
        int h = cell >> 3, kb = cell & 7;
        size_t bu = ((size_t)(h * 64 + ob) * 512 + (size_t)(kb * 64 + ibbase)) * 9;
        *(float4*)(un_s + cell * 72 + 4 * q) = *(const float4*)(unet + bu + 4 * q);
    }
    __syncthreads();

    // ---- epilogue: cell-invariant indices, zero per-iteration ALU ----
    // 162 float4 slots per cell chunk; thread owns slot tid and (tid<34) slot tid+128.
    {
        const int e0 = tid * 4;
        int kkA[4], uuA[4], kkB[4], uuB[4];
#pragma unroll
        for (int t = 0; t < 4; ++t) {
            int e = e0 + t;
            kkA[t] = e / 9;
            uuA[t] = (e / 81) * 9 + (e % 9);
            int eb = e + 512;
            kkB[t] = eb / 9;
            uuB[t] = (eb / 81) * 9 + (eb % 9);
        }
        const bool second = (tid < 34);
        const float* esh = exe_s;   // +576 per h
        const float* ush = un_s;
        float* outp = out + ((size_t)(ob * 512 + ibbase)) * 81 + e0;

#pragma unroll 1
        for (int h = 0; h < 8; ++h) {
#pragma unroll
            for (int kb = 0; kb < 8; ++kb) {
                const float* es = esh + kb * 72;   // compile-time smem offsets
                const float* us = ush + kb * 72;
                float v0 = es[kkA[0]] * us[uuA[0]];
                float v1 = es[kkA[1]] * us[uuA[1]];
                float v2 = es[kkA[2]] * us[uuA[2]];
                float v3 = es[kkA[3]] * us[uuA[3]];
                *(float4*)(outp + kb * 5184) = make_float4(v0, v1, v2, v3);
                if (second) {
                    float w0 = es[kkB[0]] * us[uuB[0]];
                    float w1 = es[kkB[1]] * us[uuB[1]];
                    float w2 = es[kkB[2]] * us[uuB[2]];
                    float w3 = es[kkB[3]] * us[uuB[3]];
                    *(float4*)(outp + kb * 5184 + 512) = make_float4(w0, w1, w2, w3);
                }
            }
            esh  += 576;                     // 8 cells * 72
            ush  += 576;
            outp += (size_t)64 * 512 * 81;   // h stride in out
        }
    }
}

// ---------------------------------------------------------------------------
extern "C" void kernel_launch(void* const* d_in, const int* in_sizes, int n_in,
                              void* d_out, int out_size)
{
    const float* z_all = (const float*)d_in[0];   // [64, 64]
    const float* W1    = (const float*)d_in[1];   // [128, 80]
    const float* b1    = (const float*)d_in[2];   // [128]
    const float* W2    = (const float*)d_in[3];   // [36864, 128]
    const float* b2    = (const float*)d_in[4];   // [36864]
    const float* unet  = (const float*)d_in[5];   // [512, 512, 9]
    const float* pde   = (const float*)d_in[6];   // [16]
    float* out = (float*)d_out;                   // [512, 512, 9, 9]

    cudaFuncSetAttribute(fused_weight_gen,
                         cudaFuncAttributeMaxDynamicSharedMemorySize, 54528);

    hypernet_hid<<<64, 128>>>(z_all, W1, b1, pde);
    fused_weight_gen<<<512, 128, 54528>>>(W2, b2, unet, out);
}